// round 7
// baseline (speedup 1.0000x reference)
#include <cuda_runtime.h>
#include <math.h>

#define N_NODES 50000
#define N_EDGES 800000
#define D 64
#define N_CHUNKS ((N_NODES + 255) / 256)   // 196
#define T_STRIDE 68

typedef unsigned long long ull;

// ------------------------- device scratch (no allocs allowed) ---------------
// Referenced ONLY from device code (host-side use of a __device__ symbol
// passes the host shadow address, which ATS dereferences silently - R1/2 bug).
// g_wh is DOUBLE-BUFFERED: same-launch epilogue writes must not alias the
// aggregation reads (R6 race).
__device__ float g_wh[N_NODES * D];
__device__ float g_wh2[N_NODES * D];
__device__ int   g_rowptr[N_NODES + 1];
__device__ int   g_cnt[N_NODES];
__device__ int   g_cursor[N_NODES];
__device__ int   g_srcsorted[N_EDGES];
__device__ int   g_chunksum[N_CHUNKS];
__device__ int   g_chunkoff[N_CHUNKS];
// pre-transposed weights / pre-combined biases (built once per launch)
__device__ float g_wihT[64 * 192];
__device__ float g_whhT[64 * 192];
__device__ float g_wT[64 * 64];
__device__ float g_brz[128];
__device__ float g_bni[64];
__device__ float g_bnh[64];

// ------------------------- f32x2 helpers ------------------------------------
__device__ __forceinline__ ull ffma2(ull a, ull b, ull c) {
    ull d;
    asm("fma.rn.f32x2 %0, %1, %2, %3;" : "=l"(d) : "l"(a), "l"(b), "l"(c));
    return d;
}
__device__ __forceinline__ ull pack2f(float x, float y) {
    ull r;
    asm("mov.b64 %0, {%1, %2};" : "=l"(r) : "f"(x), "f"(y));
    return r;
}
__device__ __forceinline__ float2 unpack2(ull v) {
    float2 f;
    asm("mov.b64 {%0, %1}, %2;" : "=f"(f.x), "=f"(f.y) : "l"(v));
    return f;
}
__device__ __forceinline__ float sigmoidf_(float x) {
    return 1.0f / (1.0f + __expf(-x));
}

// ------------------------- prep: transposes + biases + zero counts ----------
__global__ void prep_kernel(const float* __restrict__ W,
                            const float* __restrict__ Wih,
                            const float* __restrict__ Whh,
                            const float* __restrict__ bih,
                            const float* __restrict__ bhh) {
    int i = blockIdx.x * blockDim.x + threadIdx.x;
    if (i < N_NODES) g_cnt[i] = 0;
    if (i < 12288) {
        int k = i / 192, j = i % 192;
        g_wihT[i] = Wih[j * 64 + k];
    } else if (i < 24576) {
        int e = i - 12288; int k = e / 192, j = e % 192;
        g_whhT[e] = Whh[j * 64 + k];
    } else if (i < 28672) {
        int e = i - 24576; int k = e / 64, j = e % 64;
        g_wT[e] = W[j * 64 + k];
    } else if (i < 28800) {
        int d = i - 28672;
        g_brz[d] = bih[d] + bhh[d];
    } else if (i < 28864) {
        int d = i - 28800;
        g_bni[d] = bih[128 + d];
    } else if (i < 28928) {
        int d = i - 28864;
        g_bnh[d] = bhh[128 + d];
    }
}

// ------------------------- CSR build (parallel scan) -------------------------
__global__ void count_kernel(const int* __restrict__ dst) {
    int e = blockIdx.x * blockDim.x + threadIdx.x;
    if (e < N_EDGES) atomicAdd(&g_cnt[dst[e]], 1);
}

__global__ void chunksum_kernel() {
    __shared__ int ws[8];
    int b = blockIdx.x, t = threadIdx.x;
    int i = b * 256 + t;
    int v = (i < N_NODES) ? g_cnt[i] : 0;
    int x = v;
#pragma unroll
    for (int off = 16; off > 0; off >>= 1) x += __shfl_down_sync(0xffffffffu, x, off);
    if ((t & 31) == 0) ws[t >> 5] = x;
    __syncthreads();
    if (t < 8) {
        int s = ws[t];
#pragma unroll
        for (int off = 4; off > 0; off >>= 1) s += __shfl_down_sync(0xffu, s, off);
        if (t == 0) g_chunksum[b] = s;
    }
}

__global__ void chunkscan_kernel() {
    __shared__ int ws[8];
    int t = threadIdx.x, lane = t & 31, w = t >> 5;
    int v = (t < N_CHUNKS) ? g_chunksum[t] : 0;
    int x = v;
#pragma unroll
    for (int off = 1; off < 32; off <<= 1) {
        int y = __shfl_up_sync(0xffffffffu, x, off);
        if (lane >= off) x += y;
    }
    if (lane == 31) ws[w] = x;
    __syncthreads();
    if (w == 0 && lane < 8) {
        int s = ws[lane];
        int xs = s;
#pragma unroll
        for (int off = 1; off < 8; off <<= 1) {
            int y = __shfl_up_sync(0xffu, xs, off);
            if (lane >= off) xs += y;
        }
        ws[lane] = xs - s;
    }
    __syncthreads();
    if (t < N_CHUNKS) g_chunkoff[t] = x + ws[w] - v;
    if (t == 0) g_rowptr[0] = 0;
}

__global__ void rowptr_kernel() {
    __shared__ int ws[8];
    int b = blockIdx.x, t = threadIdx.x, lane = t & 31, w = t >> 5;
    int i = b * 256 + t;
    int v = (i < N_NODES) ? g_cnt[i] : 0;
    int x = v;
#pragma unroll
    for (int off = 1; off < 32; off <<= 1) {
        int y = __shfl_up_sync(0xffffffffu, x, off);
        if (lane >= off) x += y;
    }
    if (lane == 31) ws[w] = x;
    __syncthreads();
    if (w == 0 && lane < 8) {
        int s = ws[lane];
        int xs = s;
#pragma unroll
        for (int off = 1; off < 8; off <<= 1) {
            int y = __shfl_up_sync(0xffu, xs, off);
            if (lane >= off) xs += y;
        }
        ws[lane] = xs - s;
    }
    __syncthreads();
    if (i < N_NODES) {
        int incl = x + ws[w] + g_chunkoff[b];
        g_rowptr[i + 1] = incl;
        g_cursor[i]     = incl - v;
    }
}

__global__ void fill_kernel(const int* __restrict__ src, const int* __restrict__ dst) {
    int e = blockIdx.x * blockDim.x + threadIdx.x;
    if (e < N_EDGES) {
        int d = dst[e];
        int pos = atomicAdd(&g_cursor[d], 1);
        g_srcsorted[pos] = src[e];
    }
}

// ------------------------- initial wh = node_in @ W^T + b (into buf 0) ------
__global__ void __launch_bounds__(512) gemm1_kernel(
    const float* __restrict__ hin, const float* __restrict__ b) {
    extern __shared__ float sg[];
    float* wTs = sg;                  // [64][64]
    float* Xs  = wTs + 64 * 64;       // [128][T_STRIDE]
    float* sb  = Xs + 128 * T_STRIDE; // [64]

    int t = threadIdx.x;
    int row0 = blockIdx.x * 128;

    if (t < 64) sb[t] = b[t];
    for (int i = t; i < 1024; i += 512)
        ((float4*)wTs)[i] = ((const float4*)g_wT)[i];
    for (int i = t; i < 128 * 16; i += 512) {
        int r = i >> 4, c4 = i & 15;
        int g = row0 + r;
        float4 v = (g < N_NODES) ? ((const float4*)hin)[(size_t)g * 16 + c4]
                                 : make_float4(0.f, 0.f, 0.f, 0.f);
        *(float4*)&Xs[r * T_STRIDE + c4 * 4] = v;
    }
    __syncthreads();

    int ds = t & 15;
    int rs = t >> 4;
    int db = ds << 2;

    ull acc[4][2];
    {
        ull b0 = pack2f(sb[db], sb[db + 1]);
        ull b1 = pack2f(sb[db + 2], sb[db + 3]);
#pragma unroll
        for (int i = 0; i < 4; i++) { acc[i][0] = b0; acc[i][1] = b1; }
    }
#pragma unroll 8
    for (int k = 0; k < 64; k++) {
        const ull* wr = (const ull*)&wTs[k * 64 + db];
        ull w0 = wr[0], w1 = wr[1];
#pragma unroll
        for (int i = 0; i < 4; i++) {
            float x = Xs[(rs + 32 * i) * T_STRIDE + k];
            ull x2 = pack2f(x, x);
            acc[i][0] = ffma2(x2, w0, acc[i][0]);
            acc[i][1] = ffma2(x2, w1, acc[i][1]);
        }
    }
#pragma unroll
    for (int i = 0; i < 4; i++) {
        int g = row0 + rs + 32 * i;
        if (g < N_NODES) {
            float2 a = unpack2(acc[i][0]);
            float2 c = unpack2(acc[i][1]);
            *(float4*)&g_wh[(size_t)g * 64 + db] = make_float4(a.x, a.y, c.x, c.y);
        }
    }
}

// ------------------------- fused step: agg + GRU + next wh -------------------
// 512 threads, 128 rows/CTA. Aggregation reads wh buffer `buf`, epilogue
// writes the OTHER buffer (no same-launch aliasing).
__global__ void __launch_bounds__(512) step_kernel(
    const float* __restrict__ hin, float* __restrict__ hout,
    const float* __restrict__ b, int buf, int do_wh) {
    extern __shared__ float sm[];
    float* WihT_s = sm;                      // [64][192]
    float* WhhT_s = WihT_s + 64 * 192;       // [64][192]
    float* WTs    = WhhT_s + 64 * 192;       // [64][64]
    float* As     = WTs + 64 * 64;           // [128][T_STRIDE]  agg -> h_out
    float* Hs     = As + 128 * T_STRIDE;     // [128][T_STRIDE]
    float* sbrz   = Hs + 128 * T_STRIDE;     // [128]
    float* sbni   = sbrz + 128;              // [64]
    float* sbnh   = sbni + 64;               // [64]
    float* sbb    = sbnh + 64;               // [64]

    const float* whsrc = buf ? g_wh2 : g_wh;
    float*       whdst = buf ? g_wh  : g_wh2;

    int t = threadIdx.x;
    int lane = t & 31;
    int w = t >> 5;                          // 16 warps
    int row0 = blockIdx.x * 128;

    // ---- aggregation first (long-latency gathers issue early) ----
    // warp w handles nodes row0 + w*8 .. +7; lane holds dims 2*lane, 2*lane+1
#pragma unroll 1
    for (int nn = 0; nn < 8; nn++) {
        int n = row0 + w * 8 + nn;
        float ax = 0.f, ay = 0.f;
        if (n < N_NODES) {
            int p = g_rowptr[n];
            int e = g_rowptr[n + 1];
            for (; p + 4 <= e; p += 4) {
                int s0 = g_srcsorted[p];
                int s1 = g_srcsorted[p + 1];
                int s2 = g_srcsorted[p + 2];
                int s3 = g_srcsorted[p + 3];
                float2 m0 = *(const float2*)&whsrc[(size_t)s0 * 64 + lane * 2];
                float2 m1 = *(const float2*)&whsrc[(size_t)s1 * 64 + lane * 2];
                float2 m2 = *(const float2*)&whsrc[(size_t)s2 * 64 + lane * 2];
                float2 m3 = *(const float2*)&whsrc[(size_t)s3 * 64 + lane * 2];
                ax += m0.x + m1.x + m2.x + m3.x;
                ay += m0.y + m1.y + m2.y + m3.y;
            }
            for (; p < e; p++) {
                int s0 = g_srcsorted[p];
                float2 m0 = *(const float2*)&whsrc[(size_t)s0 * 64 + lane * 2];
                ax += m0.x; ay += m0.y;
            }
        }
        *(float2*)&As[(w * 8 + nn) * T_STRIDE + lane * 2] = make_float2(ax, ay);
    }

    // ---- weight / bias / h preamble ----
    for (int i = t; i < 3072; i += 512)
        ((float4*)WihT_s)[i] = ((const float4*)g_wihT)[i];
    for (int i = t; i < 3072; i += 512)
        ((float4*)WhhT_s)[i] = ((const float4*)g_whhT)[i];
    for (int i = t; i < 1024; i += 512)
        ((float4*)WTs)[i] = ((const float4*)g_wT)[i];
    if (t < 128) sbrz[t] = g_brz[t];
    else if (t < 192) sbni[t - 128] = g_bni[t - 128];
    else if (t < 256) sbnh[t - 192] = g_bnh[t - 192];
    else if (t < 320) sbb[t - 256] = b[t - 256];
    for (int i = t; i < 128 * 16; i += 512) {
        int r = i >> 4, c4 = i & 15;
        int g = row0 + r;
        float4 hv = (g < N_NODES) ? *(const float4*)&hin[(size_t)g * 64 + c4 * 4]
                                  : make_float4(0.f, 0.f, 0.f, 0.f);
        *(float4*)&Hs[r * T_STRIDE + c4 * 4] = hv;
    }
    __syncthreads();

    int ds = t & 15;
    int rs = t >> 4;
    int db = ds << 2;

    ull accR[4][2], accZ[4][2], accNi[4][2], accNh[4][2];
#pragma unroll
    for (int i = 0; i < 4; i++)
#pragma unroll
        for (int p = 0; p < 2; p++) {
            accR[i][p] = 0ull; accZ[i][p] = 0ull;
            accNi[i][p] = 0ull; accNh[i][p] = 0ull;
        }

#pragma unroll 4
    for (int k = 0; k < 64; k++) {
        const ull* wiR = (const ull*)&WihT_s[k * 192 + db];
        const ull* wiZ = (const ull*)&WihT_s[k * 192 + 64 + db];
        const ull* wiN = (const ull*)&WihT_s[k * 192 + 128 + db];
        const ull* whR = (const ull*)&WhhT_s[k * 192 + db];
        const ull* whZ = (const ull*)&WhhT_s[k * 192 + 64 + db];
        const ull* whN = (const ull*)&WhhT_s[k * 192 + 128 + db];
        ull wir0 = wiR[0], wir1 = wiR[1];
        ull wiz0 = wiZ[0], wiz1 = wiZ[1];
        ull win0 = wiN[0], win1 = wiN[1];
        ull whr0 = whR[0], whr1 = whR[1];
        ull whz0 = whZ[0], whz1 = whZ[1];
        ull whn0 = whN[0], whn1 = whN[1];
#pragma unroll
        for (int i = 0; i < 4; i++) {
            int r = rs + 32 * i;
            float av = As[r * T_STRIDE + k];
            float hv = Hs[r * T_STRIDE + k];
            ull a2 = pack2f(av, av);
            ull h2 = pack2f(hv, hv);
            accR[i][0] = ffma2(a2, wir0, accR[i][0]);
            accR[i][1] = ffma2(a2, wir1, accR[i][1]);
            accR[i][0] = ffma2(h2, whr0, accR[i][0]);
            accR[i][1] = ffma2(h2, whr1, accR[i][1]);
            accZ[i][0] = ffma2(a2, wiz0, accZ[i][0]);
            accZ[i][1] = ffma2(a2, wiz1, accZ[i][1]);
            accZ[i][0] = ffma2(h2, whz0, accZ[i][0]);
            accZ[i][1] = ffma2(h2, whz1, accZ[i][1]);
            accNi[i][0] = ffma2(a2, win0, accNi[i][0]);
            accNi[i][1] = ffma2(a2, win1, accNi[i][1]);
            accNh[i][0] = ffma2(h2, whn0, accNh[i][0]);
            accNh[i][1] = ffma2(h2, whn1, accNh[i][1]);
        }
    }

    // gate math in registers (before any As overwrite)
    float outv[4][4];
#pragma unroll
    for (int i = 0; i < 4; i++) {
        int r = rs + 32 * i;
#pragma unroll
        for (int p = 0; p < 2; p++) {
            float2 rr = unpack2(accR[i][p]);
            float2 zz = unpack2(accZ[i][p]);
            float2 ni = unpack2(accNi[i][p]);
            float2 nh = unpack2(accNh[i][p]);
            int d = db + 2 * p;
            float r0 = sigmoidf_(rr.x + sbrz[d]);
            float r1 = sigmoidf_(rr.y + sbrz[d + 1]);
            float z0 = sigmoidf_(zz.x + sbrz[64 + d]);
            float z1 = sigmoidf_(zz.y + sbrz[64 + d + 1]);
            float n0 = tanhf(ni.x + sbni[d]     + r0 * (nh.x + sbnh[d]));
            float n1 = tanhf(ni.y + sbni[d + 1] + r1 * (nh.y + sbnh[d + 1]));
            float h0 = Hs[r * T_STRIDE + d];
            float h1 = Hs[r * T_STRIDE + d + 1];
            outv[i][2 * p]     = (1.0f - z0) * n0 + z0 * h0;
            outv[i][2 * p + 1] = (1.0f - z1) * n1 + z1 * h1;
        }
    }

    // write h_out to gmem; stage into As (reuse) for the epilogue gemm
    __syncthreads();   // everyone done reading As/Hs
#pragma unroll
    for (int i = 0; i < 4; i++) {
        int r = rs + 32 * i;
        int g = row0 + r;
        float4 o4 = make_float4(outv[i][0], outv[i][1], outv[i][2], outv[i][3]);
        if (g < N_NODES)
            *(float4*)&hout[(size_t)g * 64 + db] = o4;
        *(float4*)&As[r * T_STRIDE + db] = o4;   // zero-padded rows stay finite
    }

    if (!do_wh) return;
    __syncthreads();

    // epilogue: wh_next = h_out @ W^T + b, into the OTHER buffer
    ull acc[4][2];
    {
        ull b0 = pack2f(sbb[db], sbb[db + 1]);
        ull b1 = pack2f(sbb[db + 2], sbb[db + 3]);
#pragma unroll
        for (int i = 0; i < 4; i++) { acc[i][0] = b0; acc[i][1] = b1; }
    }
#pragma unroll 8
    for (int k = 0; k < 64; k++) {
        const ull* wr = (const ull*)&WTs[k * 64 + db];
        ull w0 = wr[0], w1 = wr[1];
#pragma unroll
        for (int i = 0; i < 4; i++) {
            float x = As[(rs + 32 * i) * T_STRIDE + k];
            ull x2 = pack2f(x, x);
            acc[i][0] = ffma2(x2, w0, acc[i][0]);
            acc[i][1] = ffma2(x2, w1, acc[i][1]);
        }
    }
#pragma unroll
    for (int i = 0; i < 4; i++) {
        int g = row0 + rs + 32 * i;
        if (g < N_NODES) {
            float2 a = unpack2(acc[i][0]);
            float2 c = unpack2(acc[i][1]);
            *(float4*)&whdst[(size_t)g * 64 + db] = make_float4(a.x, a.y, c.x, c.y);
        }
    }
}

// ------------------------- launch --------------------------------------------
extern "C" void kernel_launch(void* const* d_in, const int* in_sizes, int n_in,
                              void* d_out, int out_size) {
    const float *node_in = 0, *W = 0, *b = 0, *Wih = 0, *Whh = 0, *bih = 0, *bhh = 0;
    const int *src = 0, *dst = 0;
    int n12288 = 0, n192 = 0, n800k = 0;
    for (int i = 0; i < n_in; i++) {
        switch (in_sizes[i]) {
            case N_NODES * D: node_in = (const float*)d_in[i]; break;
            case D * D:       W = (const float*)d_in[i]; break;
            case D:           b = (const float*)d_in[i]; break;
            case 3 * D * D:
                if (n12288++ == 0) Wih = (const float*)d_in[i];
                else               Whh = (const float*)d_in[i];
                break;
            case 3 * D:
                if (n192++ == 0) bih = (const float*)d_in[i];
                else             bhh = (const float*)d_in[i];
                break;
            case N_EDGES:
                if (n800k++ == 0) src = (const int*)d_in[i];
                else              dst = (const int*)d_in[i];
                break;
            default: break;
        }
    }
    float* h = (float*)d_out;

    const int GEMM1_SMEM = (64 * 64 + 128 * T_STRIDE + 64) * 4;
    const int STEP_SMEM  = (2 * 12288 + 64 * 64 + 2 * 128 * T_STRIDE + 320) * 4; // 185,600 B
    cudaFuncSetAttribute(gemm1_kernel, cudaFuncAttributeMaxDynamicSharedMemorySize, GEMM1_SMEM);
    cudaFuncSetAttribute(step_kernel,  cudaFuncAttributeMaxDynamicSharedMemorySize, STEP_SMEM);

    // one-time prep + parallel CSR build
    prep_kernel<<<(N_NODES + 255) / 256, 256>>>(W, Wih, Whh, bih, bhh);
    count_kernel<<<(N_EDGES + 255) / 256, 256>>>(dst);
    chunksum_kernel<<<N_CHUNKS, 256>>>();
    chunkscan_kernel<<<1, 256>>>();
    rowptr_kernel<<<N_CHUNKS, 256>>>();
    fill_kernel<<<(N_EDGES + 255) / 256, 256>>>(src, dst);

    const int tile_grid = (N_NODES + 127) / 128;          // 391

    gemm1_kernel<<<tile_grid, 512, GEMM1_SMEM>>>(node_in, b);     // -> buf 0
    step_kernel<<<tile_grid, 512, STEP_SMEM>>>(node_in, h, b, 0, 1); // read 0, write 1
    step_kernel<<<tile_grid, 512, STEP_SMEM>>>(h,       h, b, 1, 1); // read 1, write 0
    step_kernel<<<tile_grid, 512, STEP_SMEM>>>(h,       h, b, 0, 0); // read 0
}

// round 8
// speedup vs baseline: 1.2483x; 1.2483x over previous
#include <cuda_runtime.h>
#include <math.h>

#define N_NODES 50000
#define N_EDGES 800000
#define D 64
#define N_CHUNKS ((N_NODES + 255) / 256)   // 196
#define T_STRIDE 68

typedef unsigned long long ull;

// ------------------------- device scratch (no allocs allowed) ---------------
// Referenced ONLY from device code (host-side use of a __device__ symbol
// passes the host shadow address, which ATS dereferences silently - R1/2 bug).
__device__ float g_wh[N_NODES * D];
__device__ float g_agg[N_NODES * D];
__device__ int   g_rowptr[N_NODES + 1];
__device__ int   g_cnt[N_NODES];
__device__ int   g_cursor[N_NODES];
__device__ int   g_srcsorted[N_EDGES];
__device__ int   g_chunksum[N_CHUNKS];
__device__ int   g_chunkoff[N_CHUNKS];
// pre-transposed weights / pre-combined biases (built once per launch)
__device__ float g_wihT[64 * 192];
__device__ float g_whhT[64 * 192];
__device__ float g_wT[64 * 64];
__device__ float g_brz[128];
__device__ float g_bni[64];
__device__ float g_bnh[64];

// ------------------------- f32x2 helpers ------------------------------------
__device__ __forceinline__ ull ffma2(ull a, ull b, ull c) {
    ull d;
    asm("fma.rn.f32x2 %0, %1, %2, %3;" : "=l"(d) : "l"(a), "l"(b), "l"(c));
    return d;
}
__device__ __forceinline__ ull pack2f(float x, float y) {
    ull r;
    asm("mov.b64 %0, {%1, %2};" : "=l"(r) : "f"(x), "f"(y));
    return r;
}
__device__ __forceinline__ float2 unpack2(ull v) {
    float2 f;
    asm("mov.b64 {%0, %1}, %2;" : "=f"(f.x), "=f"(f.y) : "l"(v));
    return f;
}
__device__ __forceinline__ float sigmoidf_(float x) {
    return 1.0f / (1.0f + __expf(-x));
}

// ------------------------- prep: transposes + biases + zero counts ----------
__global__ void prep_kernel(const float* __restrict__ W,
                            const float* __restrict__ Wih,
                            const float* __restrict__ Whh,
                            const float* __restrict__ bih,
                            const float* __restrict__ bhh) {
    int i = blockIdx.x * blockDim.x + threadIdx.x;
    if (i < N_NODES) g_cnt[i] = 0;
    if (i < 12288) {
        int k = i / 192, j = i % 192;
        g_wihT[i] = Wih[j * 64 + k];
    } else if (i < 24576) {
        int e = i - 12288; int k = e / 192, j = e % 192;
        g_whhT[e] = Whh[j * 64 + k];
    } else if (i < 28672) {
        int e = i - 24576; int k = e / 64, j = e % 64;
        g_wT[e] = W[j * 64 + k];
    } else if (i < 28800) {
        int d = i - 28672;
        g_brz[d] = bih[d] + bhh[d];
    } else if (i < 28864) {
        int d = i - 28800;
        g_bni[d] = bih[128 + d];
    } else if (i < 28928) {
        int d = i - 28864;
        g_bnh[d] = bhh[128 + d];
    }
}

// ------------------------- CSR build (parallel scan) -------------------------
__global__ void count_kernel(const int* __restrict__ dst) {
    int e = blockIdx.x * blockDim.x + threadIdx.x;
    if (e < N_EDGES) atomicAdd(&g_cnt[dst[e]], 1);
}

__global__ void chunksum_kernel() {
    __shared__ int ws[8];
    int b = blockIdx.x, t = threadIdx.x;
    int i = b * 256 + t;
    int v = (i < N_NODES) ? g_cnt[i] : 0;
    int x = v;
#pragma unroll
    for (int off = 16; off > 0; off >>= 1) x += __shfl_down_sync(0xffffffffu, x, off);
    if ((t & 31) == 0) ws[t >> 5] = x;
    __syncthreads();
    if (t < 8) {
        int s = ws[t];
#pragma unroll
        for (int off = 4; off > 0; off >>= 1) s += __shfl_down_sync(0xffu, s, off);
        if (t == 0) g_chunksum[b] = s;
    }
}

__global__ void chunkscan_kernel() {
    __shared__ int ws[8];
    int t = threadIdx.x, lane = t & 31, w = t >> 5;
    int v = (t < N_CHUNKS) ? g_chunksum[t] : 0;
    int x = v;
#pragma unroll
    for (int off = 1; off < 32; off <<= 1) {
        int y = __shfl_up_sync(0xffffffffu, x, off);
        if (lane >= off) x += y;
    }
    if (lane == 31) ws[w] = x;
    __syncthreads();
    if (w == 0 && lane < 8) {
        int s = ws[lane];
        int xs = s;
#pragma unroll
        for (int off = 1; off < 8; off <<= 1) {
            int y = __shfl_up_sync(0xffu, xs, off);
            if (lane >= off) xs += y;
        }
        ws[lane] = xs - s;
    }
    __syncthreads();
    if (t < N_CHUNKS) g_chunkoff[t] = x + ws[w] - v;
    if (t == 0) g_rowptr[0] = 0;
}

__global__ void rowptr_kernel() {
    __shared__ int ws[8];
    int b = blockIdx.x, t = threadIdx.x, lane = t & 31, w = t >> 5;
    int i = b * 256 + t;
    int v = (i < N_NODES) ? g_cnt[i] : 0;
    int x = v;
#pragma unroll
    for (int off = 1; off < 32; off <<= 1) {
        int y = __shfl_up_sync(0xffffffffu, x, off);
        if (lane >= off) x += y;
    }
    if (lane == 31) ws[w] = x;
    __syncthreads();
    if (w == 0 && lane < 8) {
        int s = ws[lane];
        int xs = s;
#pragma unroll
        for (int off = 1; off < 8; off <<= 1) {
            int y = __shfl_up_sync(0xffu, xs, off);
            if (lane >= off) xs += y;
        }
        ws[lane] = xs - s;
    }
    __syncthreads();
    if (i < N_NODES) {
        int incl = x + ws[w] + g_chunkoff[b];
        g_rowptr[i + 1] = incl;
        g_cursor[i]     = incl - v;
    }
}

__global__ void fill_kernel(const int* __restrict__ src, const int* __restrict__ dst) {
    int e = blockIdx.x * blockDim.x + threadIdx.x;
    if (e < N_EDGES) {
        int d = dst[e];
        int pos = atomicAdd(&g_cursor[d], 1);
        g_srcsorted[pos] = src[e];
    }
}

// ------------------------- initial wh = node_in @ W^T + b -------------------
__global__ void __launch_bounds__(512) gemm1_kernel(
    const float* __restrict__ hin, const float* __restrict__ b) {
    extern __shared__ float sg[];
    float* wTs = sg;                  // [64][64]
    float* Xs  = wTs + 64 * 64;       // [128][T_STRIDE]
    float* sb  = Xs + 128 * T_STRIDE; // [64]

    int t = threadIdx.x;
    int row0 = blockIdx.x * 128;

    if (t < 64) sb[t] = b[t];
    for (int i = t; i < 1024; i += 512)
        ((float4*)wTs)[i] = ((const float4*)g_wT)[i];
    for (int i = t; i < 128 * 16; i += 512) {
        int r = i >> 4, c4 = i & 15;
        int g = row0 + r;
        float4 v = (g < N_NODES) ? ((const float4*)hin)[(size_t)g * 16 + c4]
                                 : make_float4(0.f, 0.f, 0.f, 0.f);
        *(float4*)&Xs[r * T_STRIDE + c4 * 4] = v;
    }
    __syncthreads();

    int ds = t & 15;
    int rs = t >> 4;
    int db = ds << 2;

    ull acc[4][2];
    {
        ull b0 = pack2f(sb[db], sb[db + 1]);
        ull b1 = pack2f(sb[db + 2], sb[db + 3]);
#pragma unroll
        for (int i = 0; i < 4; i++) { acc[i][0] = b0; acc[i][1] = b1; }
    }
#pragma unroll 8
    for (int k = 0; k < 64; k++) {
        const ull* wr = (const ull*)&wTs[k * 64 + db];
        ull w0 = wr[0], w1 = wr[1];
#pragma unroll
        for (int i = 0; i < 4; i++) {
            float x = Xs[(rs + 32 * i) * T_STRIDE + k];
            ull x2 = pack2f(x, x);
            acc[i][0] = ffma2(x2, w0, acc[i][0]);
            acc[i][1] = ffma2(x2, w1, acc[i][1]);
        }
    }
#pragma unroll
    for (int i = 0; i < 4; i++) {
        int g = row0 + rs + 32 * i;
        if (g < N_NODES) {
            float2 a = unpack2(acc[i][0]);
            float2 c = unpack2(acc[i][1]);
            *(float4*)&g_wh[(size_t)g * 64 + db] = make_float4(a.x, a.y, c.x, c.y);
        }
    }
}

// ------------------------- aggregation: one warp per dst node ---------------
// High occupancy is what hides the L2 gather latency (R7 lesson: do NOT move
// this into the 1-CTA/SM GRU kernel).
__global__ void __launch_bounds__(256) agg_kernel() {
    int gw = (blockIdx.x * blockDim.x + threadIdx.x) >> 5;
    if (gw >= N_NODES) return;
    int lane = threadIdx.x & 31;
    int p = g_rowptr[gw];
    int e = g_rowptr[gw + 1];
    float ax = 0.0f, ay = 0.0f;
    for (; p + 4 <= e; p += 4) {
        int s0 = g_srcsorted[p];
        int s1 = g_srcsorted[p + 1];
        int s2 = g_srcsorted[p + 2];
        int s3 = g_srcsorted[p + 3];
        float2 m0 = *(const float2*)&g_wh[(size_t)s0 * 64 + lane * 2];
        float2 m1 = *(const float2*)&g_wh[(size_t)s1 * 64 + lane * 2];
        float2 m2 = *(const float2*)&g_wh[(size_t)s2 * 64 + lane * 2];
        float2 m3 = *(const float2*)&g_wh[(size_t)s3 * 64 + lane * 2];
        ax += m0.x + m1.x + m2.x + m3.x;
        ay += m0.y + m1.y + m2.y + m3.y;
    }
    for (; p < e; p++) {
        int s0 = g_srcsorted[p];
        float2 m0 = *(const float2*)&g_wh[(size_t)s0 * 64 + lane * 2];
        ax += m0.x; ay += m0.y;
    }
    *(float2*)&g_agg[(size_t)gw * 64 + lane * 2] = make_float2(ax, ay);
}

// ------------------------- fused GRU + next-step wh --------------------------
// 512 threads, 128 rows/CTA. Reads g_agg (produced by agg_kernel), computes
// h_out, then the epilogue computes wh_next = h_out @ W^T + b into g_wh.
// Single wh buffer is safe: agg of this step consumed g_wh in the PREVIOUS
// launch; kernel boundaries order agg(s) -> gru(s) -> agg(s+1).
__global__ void __launch_bounds__(512) gru_kernel(
    const float* __restrict__ hin, float* __restrict__ hout,
    const float* __restrict__ b, int do_wh) {
    extern __shared__ float sm[];
    float* WihT_s = sm;                      // [64][192]
    float* WhhT_s = WihT_s + 64 * 192;       // [64][192]
    float* WTs    = WhhT_s + 64 * 192;       // [64][64]
    float* As     = WTs + 64 * 64;           // [128][T_STRIDE]  agg -> h_out
    float* Hs     = As + 128 * T_STRIDE;     // [128][T_STRIDE]
    float* sbrz   = Hs + 128 * T_STRIDE;     // [128]
    float* sbni   = sbrz + 128;              // [64]
    float* sbnh   = sbni + 64;               // [64]
    float* sbb    = sbnh + 64;               // [64]

    int t = threadIdx.x;
    int row0 = blockIdx.x * 128;

    for (int i = t; i < 3072; i += 512)
        ((float4*)WihT_s)[i] = ((const float4*)g_wihT)[i];
    for (int i = t; i < 3072; i += 512)
        ((float4*)WhhT_s)[i] = ((const float4*)g_whhT)[i];
    for (int i = t; i < 1024; i += 512)
        ((float4*)WTs)[i] = ((const float4*)g_wT)[i];
    if (t < 128) sbrz[t] = g_brz[t];
    else if (t < 192) sbni[t - 128] = g_bni[t - 128];
    else if (t < 256) sbnh[t - 192] = g_bnh[t - 192];
    else if (t < 320) sbb[t - 256] = b[t - 256];
    for (int i = t; i < 128 * 16; i += 512) {
        int r = i >> 4, c4 = i & 15;
        int g = row0 + r;
        float4 av = (g < N_NODES) ? *(const float4*)&g_agg[(size_t)g * 64 + c4 * 4]
                                  : make_float4(0.f, 0.f, 0.f, 0.f);
        float4 hv = (g < N_NODES) ? *(const float4*)&hin[(size_t)g * 64 + c4 * 4]
                                  : make_float4(0.f, 0.f, 0.f, 0.f);
        *(float4*)&As[r * T_STRIDE + c4 * 4] = av;
        *(float4*)&Hs[r * T_STRIDE + c4 * 4] = hv;
    }
    __syncthreads();

    int ds = t & 15;
    int rs = t >> 4;
    int db = ds << 2;

    ull accR[4][2], accZ[4][2], accNi[4][2], accNh[4][2];
#pragma unroll
    for (int i = 0; i < 4; i++)
#pragma unroll
        for (int p = 0; p < 2; p++) {
            accR[i][p] = 0ull; accZ[i][p] = 0ull;
            accNi[i][p] = 0ull; accNh[i][p] = 0ull;
        }

#pragma unroll 4
    for (int k = 0; k < 64; k++) {
        const ull* wiR = (const ull*)&WihT_s[k * 192 + db];
        const ull* wiZ = (const ull*)&WihT_s[k * 192 + 64 + db];
        const ull* wiN = (const ull*)&WihT_s[k * 192 + 128 + db];
        const ull* whR = (const ull*)&WhhT_s[k * 192 + db];
        const ull* whZ = (const ull*)&WhhT_s[k * 192 + 64 + db];
        const ull* whN = (const ull*)&WhhT_s[k * 192 + 128 + db];
        ull wir0 = wiR[0], wir1 = wiR[1];
        ull wiz0 = wiZ[0], wiz1 = wiZ[1];
        ull win0 = wiN[0], win1 = wiN[1];
        ull whr0 = whR[0], whr1 = whR[1];
        ull whz0 = whZ[0], whz1 = whZ[1];
        ull whn0 = whN[0], whn1 = whN[1];
#pragma unroll
        for (int i = 0; i < 4; i++) {
            int r = rs + 32 * i;
            float av = As[r * T_STRIDE + k];
            float hv = Hs[r * T_STRIDE + k];
            ull a2 = pack2f(av, av);
            ull h2 = pack2f(hv, hv);
            accR[i][0] = ffma2(a2, wir0, accR[i][0]);
            accR[i][1] = ffma2(a2, wir1, accR[i][1]);
            accR[i][0] = ffma2(h2, whr0, accR[i][0]);
            accR[i][1] = ffma2(h2, whr1, accR[i][1]);
            accZ[i][0] = ffma2(a2, wiz0, accZ[i][0]);
            accZ[i][1] = ffma2(a2, wiz1, accZ[i][1]);
            accZ[i][0] = ffma2(h2, whz0, accZ[i][0]);
            accZ[i][1] = ffma2(h2, whz1, accZ[i][1]);
            accNi[i][0] = ffma2(a2, win0, accNi[i][0]);
            accNi[i][1] = ffma2(a2, win1, accNi[i][1]);
            accNh[i][0] = ffma2(h2, whn0, accNh[i][0]);
            accNh[i][1] = ffma2(h2, whn1, accNh[i][1]);
        }
    }

    // gate math in registers (before any As overwrite)
    float outv[4][4];
#pragma unroll
    for (int i = 0; i < 4; i++) {
        int r = rs + 32 * i;
#pragma unroll
        for (int p = 0; p < 2; p++) {
            float2 rr = unpack2(accR[i][p]);
            float2 zz = unpack2(accZ[i][p]);
            float2 ni = unpack2(accNi[i][p]);
            float2 nh = unpack2(accNh[i][p]);
            int d = db + 2 * p;
            float r0 = sigmoidf_(rr.x + sbrz[d]);
            float r1 = sigmoidf_(rr.y + sbrz[d + 1]);
            float z0 = sigmoidf_(zz.x + sbrz[64 + d]);
            float z1 = sigmoidf_(zz.y + sbrz[64 + d + 1]);
            float n0 = tanhf(ni.x + sbni[d]     + r0 * (nh.x + sbnh[d]));
            float n1 = tanhf(ni.y + sbni[d + 1] + r1 * (nh.y + sbnh[d + 1]));
            float h0 = Hs[r * T_STRIDE + d];
            float h1 = Hs[r * T_STRIDE + d + 1];
            outv[i][2 * p]     = (1.0f - z0) * n0 + z0 * h0;
            outv[i][2 * p + 1] = (1.0f - z1) * n1 + z1 * h1;
        }
    }

    // write h_out to gmem; stage into As (reuse) for the epilogue gemm
    __syncthreads();   // everyone done reading As/Hs
#pragma unroll
    for (int i = 0; i < 4; i++) {
        int r = rs + 32 * i;
        int g = row0 + r;
        float4 o4 = make_float4(outv[i][0], outv[i][1], outv[i][2], outv[i][3]);
        if (g < N_NODES)
            *(float4*)&hout[(size_t)g * 64 + db] = o4;
        *(float4*)&As[r * T_STRIDE + db] = o4;   // zero-padded rows stay finite
    }

    if (!do_wh) return;
    __syncthreads();

    // epilogue: wh_next = h_out @ W^T + b
    ull acc[4][2];
    {
        ull b0 = pack2f(sbb[db], sbb[db + 1]);
        ull b1 = pack2f(sbb[db + 2], sbb[db + 3]);
#pragma unroll
        for (int i = 0; i < 4; i++) { acc[i][0] = b0; acc[i][1] = b1; }
    }
#pragma unroll 8
    for (int k = 0; k < 64; k++) {
        const ull* wr = (const ull*)&WTs[k * 64 + db];
        ull w0 = wr[0], w1 = wr[1];
#pragma unroll
        for (int i = 0; i < 4; i++) {
            float x = As[(rs + 32 * i) * T_STRIDE + k];
            ull x2 = pack2f(x, x);
            acc[i][0] = ffma2(x2, w0, acc[i][0]);
            acc[i][1] = ffma2(x2, w1, acc[i][1]);
        }
    }
#pragma unroll
    for (int i = 0; i < 4; i++) {
        int g = row0 + rs + 32 * i;
        if (g < N_NODES) {
            float2 a = unpack2(acc[i][0]);
            float2 c = unpack2(acc[i][1]);
            *(float4*)&g_wh[(size_t)g * 64 + db] = make_float4(a.x, a.y, c.x, c.y);
        }
    }
}

// ------------------------- launch --------------------------------------------
extern "C" void kernel_launch(void* const* d_in, const int* in_sizes, int n_in,
                              void* d_out, int out_size) {
    const float *node_in = 0, *W = 0, *b = 0, *Wih = 0, *Whh = 0, *bih = 0, *bhh = 0;
    const int *src = 0, *dst = 0;
    int n12288 = 0, n192 = 0, n800k = 0;
    for (int i = 0; i < n_in; i++) {
        switch (in_sizes[i]) {
            case N_NODES * D: node_in = (const float*)d_in[i]; break;
            case D * D:       W = (const float*)d_in[i]; break;
            case D:           b = (const float*)d_in[i]; break;
            case 3 * D * D:
                if (n12288++ == 0) Wih = (const float*)d_in[i];
                else               Whh = (const float*)d_in[i];
                break;
            case 3 * D:
                if (n192++ == 0) bih = (const float*)d_in[i];
                else             bhh = (const float*)d_in[i];
                break;
            case N_EDGES:
                if (n800k++ == 0) src = (const int*)d_in[i];
                else              dst = (const int*)d_in[i];
                break;
            default: break;
        }
    }
    float* h = (float*)d_out;

    const int GEMM1_SMEM = (64 * 64 + 128 * T_STRIDE + 64) * 4;
    const int GRU_SMEM   = (2 * 12288 + 64 * 64 + 2 * 128 * T_STRIDE + 320) * 4; // 185,600 B
    cudaFuncSetAttribute(gemm1_kernel, cudaFuncAttributeMaxDynamicSharedMemorySize, GEMM1_SMEM);
    cudaFuncSetAttribute(gru_kernel,   cudaFuncAttributeMaxDynamicSharedMemorySize, GRU_SMEM);

    // one-time prep + parallel CSR build
    prep_kernel<<<(N_NODES + 255) / 256, 256>>>(W, Wih, Whh, bih, bhh);
    count_kernel<<<(N_EDGES + 255) / 256, 256>>>(dst);
    chunksum_kernel<<<N_CHUNKS, 256>>>();
    chunkscan_kernel<<<1, 256>>>();
    rowptr_kernel<<<N_CHUNKS, 256>>>();
    fill_kernel<<<(N_EDGES + 255) / 256, 256>>>(src, dst);

    const int tile_grid = (N_NODES + 127) / 128;          // 391
    const int agg_grid  = (N_NODES * 32 + 255) / 256;

    gemm1_kernel<<<tile_grid, 512, GEMM1_SMEM>>>(node_in, b);   // wh for step 0

    // step 0
    agg_kernel<<<agg_grid, 256>>>();
    gru_kernel<<<tile_grid, 512, GRU_SMEM>>>(node_in, h, b, 1); // also wh for step 1
    // step 1
    agg_kernel<<<agg_grid, 256>>>();
    gru_kernel<<<tile_grid, 512, GRU_SMEM>>>(h, h, b, 1);       // also wh for step 2
    // step 2
    agg_kernel<<<agg_grid, 256>>>();
    gru_kernel<<<tile_grid, 512, GRU_SMEM>>>(h, h, b, 0);
}

// round 9
// speedup vs baseline: 1.2565x; 1.0065x over previous
#include <cuda_runtime.h>
#include <math.h>

#define N_NODES 50000
#define N_EDGES 800000
#define D 64
#define N_CHUNKS ((N_NODES + 255) / 256)   // 196
#define T_STRIDE 68
#define AH_STRIDE 136                       // 2*64 + 8 pad (16B-aligned rows)
#define N_TILES ((N_NODES + 127) / 128)    // 391
#define GRU_GRID 131                        // 131*3 >= 391, ~1 wave

typedef unsigned long long ull;

// ------------------------- device scratch (no allocs allowed) ---------------
// Referenced ONLY from device code (host-side use of a __device__ symbol
// passes the host shadow address, which ATS dereferences silently - R1/2 bug).
__device__ float g_wh[N_NODES * D];
__device__ float g_agg[N_NODES * D];
__device__ int   g_rowptr[N_NODES + 1];
__device__ int   g_cnt[N_NODES];
__device__ int   g_cursor[N_NODES];
__device__ int   g_srcsorted[N_EDGES];
__device__ int   g_chunksum[N_CHUNKS];
__device__ int   g_chunkoff[N_CHUNKS];
// pre-transposed weights / pre-combined biases (built once per launch)
__device__ float g_wihT[64 * 192];
__device__ float g_whhT[64 * 192];
__device__ float g_wT[64 * 64];
__device__ float g_brz[128];
__device__ float g_bni[64];
__device__ float g_bnh[64];

// ------------------------- f32x2 helpers ------------------------------------
__device__ __forceinline__ ull ffma2(ull a, ull b, ull c) {
    ull d;
    asm("fma.rn.f32x2 %0, %1, %2, %3;" : "=l"(d) : "l"(a), "l"(b), "l"(c));
    return d;
}
__device__ __forceinline__ ull pack2f(float x, float y) {
    ull r;
    asm("mov.b64 %0, {%1, %2};" : "=l"(r) : "f"(x), "f"(y));
    return r;
}
__device__ __forceinline__ float2 unpack2(ull v) {
    float2 f;
    asm("mov.b64 {%0, %1}, %2;" : "=f"(f.x), "=f"(f.y) : "l"(v));
    return f;
}
__device__ __forceinline__ float sigmoidf_(float x) {
    return 1.0f / (1.0f + __expf(-x));
}

// ------------------------- prep: transposes + biases + zero counts ----------
__global__ void prep_kernel(const float* __restrict__ W,
                            const float* __restrict__ Wih,
                            const float* __restrict__ Whh,
                            const float* __restrict__ bih,
                            const float* __restrict__ bhh) {
    int i = blockIdx.x * blockDim.x + threadIdx.x;
    if (i < N_NODES) g_cnt[i] = 0;
    if (i < 12288) {
        int k = i / 192, j = i % 192;
        g_wihT[i] = Wih[j * 64 + k];
    } else if (i < 24576) {
        int e = i - 12288; int k = e / 192, j = e % 192;
        g_whhT[e] = Whh[j * 64 + k];
    } else if (i < 28672) {
        int e = i - 24576; int k = e / 64, j = e % 64;
        g_wT[e] = W[j * 64 + k];
    } else if (i < 28800) {
        int d = i - 28672;
        g_brz[d] = bih[d] + bhh[d];
    } else if (i < 28864) {
        int d = i - 28800;
        g_bni[d] = bih[128 + d];
    } else if (i < 28928) {
        int d = i - 28864;
        g_bnh[d] = bhh[128 + d];
    }
}

// ------------------------- CSR build (parallel scan) -------------------------
__global__ void count_kernel(const int* __restrict__ dst) {
    int e = blockIdx.x * blockDim.x + threadIdx.x;
    if (e < N_EDGES) atomicAdd(&g_cnt[dst[e]], 1);
}

__global__ void chunksum_kernel() {
    __shared__ int ws[8];
    int b = blockIdx.x, t = threadIdx.x;
    int i = b * 256 + t;
    int v = (i < N_NODES) ? g_cnt[i] : 0;
    int x = v;
#pragma unroll
    for (int off = 16; off > 0; off >>= 1) x += __shfl_down_sync(0xffffffffu, x, off);
    if ((t & 31) == 0) ws[t >> 5] = x;
    __syncthreads();
    if (t < 8) {
        int s = ws[t];
#pragma unroll
        for (int off = 4; off > 0; off >>= 1) s += __shfl_down_sync(0xffu, s, off);
        if (t == 0) g_chunksum[b] = s;
    }
}

__global__ void chunkscan_kernel() {
    __shared__ int ws[8];
    int t = threadIdx.x, lane = t & 31, w = t >> 5;
    int v = (t < N_CHUNKS) ? g_chunksum[t] : 0;
    int x = v;
#pragma unroll
    for (int off = 1; off < 32; off <<= 1) {
        int y = __shfl_up_sync(0xffffffffu, x, off);
        if (lane >= off) x += y;
    }
    if (lane == 31) ws[w] = x;
    __syncthreads();
    if (w == 0 && lane < 8) {
        int s = ws[lane];
        int xs = s;
#pragma unroll
        for (int off = 1; off < 8; off <<= 1) {
            int y = __shfl_up_sync(0xffu, xs, off);
            if (lane >= off) xs += y;
        }
        ws[lane] = xs - s;
    }
    __syncthreads();
    if (t < N_CHUNKS) g_chunkoff[t] = x + ws[w] - v;
    if (t == 0) g_rowptr[0] = 0;
}

__global__ void rowptr_kernel() {
    __shared__ int ws[8];
    int b = blockIdx.x, t = threadIdx.x, lane = t & 31, w = t >> 5;
    int i = b * 256 + t;
    int v = (i < N_NODES) ? g_cnt[i] : 0;
    int x = v;
#pragma unroll
    for (int off = 1; off < 32; off <<= 1) {
        int y = __shfl_up_sync(0xffffffffu, x, off);
        if (lane >= off) x += y;
    }
    if (lane == 31) ws[w] = x;
    __syncthreads();
    if (w == 0 && lane < 8) {
        int s = ws[lane];
        int xs = s;
#pragma unroll
        for (int off = 1; off < 8; off <<= 1) {
            int y = __shfl_up_sync(0xffu, xs, off);
            if (lane >= off) xs += y;
        }
        ws[lane] = xs - s;
    }
    __syncthreads();
    if (i < N_NODES) {
        int incl = x + ws[w] + g_chunkoff[b];
        g_rowptr[i + 1] = incl;
        g_cursor[i]     = incl - v;
    }
}

__global__ void fill_kernel(const int* __restrict__ src, const int* __restrict__ dst) {
    int e = blockIdx.x * blockDim.x + threadIdx.x;
    if (e < N_EDGES) {
        int d = dst[e];
        int pos = atomicAdd(&g_cursor[d], 1);
        g_srcsorted[pos] = src[e];
    }
}

// ------------------------- initial wh = node_in @ W^T + b -------------------
__global__ void __launch_bounds__(512) gemm1_kernel(
    const float* __restrict__ hin, const float* __restrict__ b) {
    extern __shared__ float sg[];
    float* wTs = sg;                  // [64][64]
    float* Xs  = wTs + 64 * 64;       // [128][T_STRIDE]
    float* sb  = Xs + 128 * T_STRIDE; // [64]

    int t = threadIdx.x;
    int row0 = blockIdx.x * 128;

    if (t < 64) sb[t] = b[t];
    for (int i = t; i < 1024; i += 512)
        ((float4*)wTs)[i] = ((const float4*)g_wT)[i];
    for (int i = t; i < 128 * 16; i += 512) {
        int r = i >> 4, c4 = i & 15;
        int g = row0 + r;
        float4 v = (g < N_NODES) ? ((const float4*)hin)[(size_t)g * 16 + c4]
                                 : make_float4(0.f, 0.f, 0.f, 0.f);
        *(float4*)&Xs[r * T_STRIDE + c4 * 4] = v;
    }
    __syncthreads();

    int ds = t & 15;
    int rs = t >> 4;
    int db = ds << 2;

    ull acc[4][2];
    {
        ull b0 = pack2f(sb[db], sb[db + 1]);
        ull b1 = pack2f(sb[db + 2], sb[db + 3]);
#pragma unroll
        for (int i = 0; i < 4; i++) { acc[i][0] = b0; acc[i][1] = b1; }
    }
#pragma unroll 8
    for (int k = 0; k < 64; k++) {
        const ull* wr = (const ull*)&wTs[k * 64 + db];
        ull w0 = wr[0], w1 = wr[1];
#pragma unroll
        for (int i = 0; i < 4; i++) {
            float x = Xs[(rs + 32 * i) * T_STRIDE + k];
            ull x2 = pack2f(x, x);
            acc[i][0] = ffma2(x2, w0, acc[i][0]);
            acc[i][1] = ffma2(x2, w1, acc[i][1]);
        }
    }
#pragma unroll
    for (int i = 0; i < 4; i++) {
        int g = row0 + rs + 32 * i;
        if (g < N_NODES) {
            float2 a = unpack2(acc[i][0]);
            float2 c = unpack2(acc[i][1]);
            *(float4*)&g_wh[(size_t)g * 64 + db] = make_float4(a.x, a.y, c.x, c.y);
        }
    }
}

// ------------------------- aggregation: one warp per dst node ---------------
// High occupancy hides L2 gather latency (R7 lesson). Unroll-8 for MLP.
__global__ void __launch_bounds__(256) agg_kernel() {
    int gw = (blockIdx.x * blockDim.x + threadIdx.x) >> 5;
    if (gw >= N_NODES) return;
    int lane = threadIdx.x & 31;
    int p = g_rowptr[gw];
    int e = g_rowptr[gw + 1];
    float ax = 0.0f, ay = 0.0f;
    for (; p + 8 <= e; p += 8) {
        float2 m[8];
#pragma unroll
        for (int j = 0; j < 8; j++) {
            int s = g_srcsorted[p + j];
            m[j] = *(const float2*)&g_wh[(size_t)s * 64 + lane * 2];
        }
#pragma unroll
        for (int j = 0; j < 8; j++) { ax += m[j].x; ay += m[j].y; }
    }
    for (; p < e; p++) {
        int s0 = g_srcsorted[p];
        float2 m0 = *(const float2*)&g_wh[(size_t)s0 * 64 + lane * 2];
        ax += m0.x; ay += m0.y;
    }
    *(float2*)&g_agg[(size_t)gw * 64 + lane * 2] = make_float2(ax, ay);
}

// ------------------------- persistent fused GRU + next-step wh ---------------
// 512 threads, 131 CTAs, each processing ~3 tiles of 128 rows. Weights/biases
// loaded ONCE per CTA. A/H interleaved in one tile (halves tile wavefronts).
// Epilogue stages h_out into the AH 'a' slots (h_old 'h' slots untouched).
__global__ void __launch_bounds__(512) gru_kernel(
    const float* __restrict__ hin, float* __restrict__ hout,
    const float* __restrict__ b, int do_wh) {
    extern __shared__ float sm[];
    float* WihT_s = sm;                      // [64][192]
    float* WhhT_s = WihT_s + 64 * 192;       // [64][192]
    float* WTs    = WhhT_s + 64 * 192;       // [64][64]
    float* AH     = WTs + 64 * 64;           // [128][AH_STRIDE] interleaved a,h
    float* sbrz   = AH + 128 * AH_STRIDE;    // [128]
    float* sbni   = sbrz + 128;              // [64]
    float* sbnh   = sbni + 64;               // [64]
    float* sbb    = sbnh + 64;               // [64]

    int t = threadIdx.x;
    int ds = t & 15;
    int rs = t >> 4;
    int db = ds << 2;

    // ---- one-time weight/bias preamble ----
    for (int i = t; i < 3072; i += 512)
        ((float4*)WihT_s)[i] = ((const float4*)g_wihT)[i];
    for (int i = t; i < 3072; i += 512)
        ((float4*)WhhT_s)[i] = ((const float4*)g_whhT)[i];
    for (int i = t; i < 1024; i += 512)
        ((float4*)WTs)[i] = ((const float4*)g_wT)[i];
    if (t < 128) sbrz[t] = g_brz[t];
    else if (t < 192) sbni[t - 128] = g_bni[t - 128];
    else if (t < 256) sbnh[t - 192] = g_bnh[t - 192];
    else if (t < 320) sbb[t - 256] = b[t - 256];

    for (int tile = blockIdx.x; tile < N_TILES; tile += gridDim.x) {
        int row0 = tile * 128;

        // ---- tile preamble: interleaved a/h ----
        for (int i = t; i < 128 * 16; i += 512) {
            int r = i >> 4, c4 = i & 15;
            int g = row0 + r;
            float4 av = (g < N_NODES) ? *(const float4*)&g_agg[(size_t)g * 64 + c4 * 4]
                                      : make_float4(0.f, 0.f, 0.f, 0.f);
            float4 hv = (g < N_NODES) ? *(const float4*)&hin[(size_t)g * 64 + c4 * 4]
                                      : make_float4(0.f, 0.f, 0.f, 0.f);
            float* base = &AH[r * AH_STRIDE + c4 * 8];
            *(float2*)(base + 0) = make_float2(av.x, hv.x);
            *(float2*)(base + 2) = make_float2(av.y, hv.y);
            *(float2*)(base + 4) = make_float2(av.z, hv.z);
            *(float2*)(base + 6) = make_float2(av.w, hv.w);
        }
        __syncthreads();

        ull accR[4][2], accZ[4][2], accNi[4][2], accNh[4][2];
#pragma unroll
        for (int i = 0; i < 4; i++)
#pragma unroll
            for (int p = 0; p < 2; p++) {
                accR[i][p] = 0ull; accZ[i][p] = 0ull;
                accNi[i][p] = 0ull; accNh[i][p] = 0ull;
            }

#pragma unroll 4
        for (int k = 0; k < 64; k++) {
            const ull* wiR = (const ull*)&WihT_s[k * 192 + db];
            const ull* wiZ = (const ull*)&WihT_s[k * 192 + 64 + db];
            const ull* wiN = (const ull*)&WihT_s[k * 192 + 128 + db];
            const ull* whR = (const ull*)&WhhT_s[k * 192 + db];
            const ull* whZ = (const ull*)&WhhT_s[k * 192 + 64 + db];
            const ull* whN = (const ull*)&WhhT_s[k * 192 + 128 + db];
            ull wir0 = wiR[0], wir1 = wiR[1];
            ull wiz0 = wiZ[0], wiz1 = wiZ[1];
            ull win0 = wiN[0], win1 = wiN[1];
            ull whr0 = whR[0], whr1 = whR[1];
            ull whz0 = whZ[0], whz1 = whZ[1];
            ull whn0 = whN[0], whn1 = whN[1];
#pragma unroll
            for (int i = 0; i < 4; i++) {
                int r = rs + 32 * i;
                ull ahv = *(const ull*)&AH[r * AH_STRIDE + 2 * k];
                float2 fah = unpack2(ahv);
                ull a2 = pack2f(fah.x, fah.x);
                ull h2 = pack2f(fah.y, fah.y);
                accR[i][0] = ffma2(a2, wir0, accR[i][0]);
                accR[i][1] = ffma2(a2, wir1, accR[i][1]);
                accR[i][0] = ffma2(h2, whr0, accR[i][0]);
                accR[i][1] = ffma2(h2, whr1, accR[i][1]);
                accZ[i][0] = ffma2(a2, wiz0, accZ[i][0]);
                accZ[i][1] = ffma2(a2, wiz1, accZ[i][1]);
                accZ[i][0] = ffma2(h2, whz0, accZ[i][0]);
                accZ[i][1] = ffma2(h2, whz1, accZ[i][1]);
                accNi[i][0] = ffma2(a2, win0, accNi[i][0]);
                accNi[i][1] = ffma2(a2, win1, accNi[i][1]);
                accNh[i][0] = ffma2(h2, whn0, accNh[i][0]);
                accNh[i][1] = ffma2(h2, whn1, accNh[i][1]);
            }
        }

        // gate math in registers
        float outv[4][4];
#pragma unroll
        for (int i = 0; i < 4; i++) {
            int r = rs + 32 * i;
#pragma unroll
            for (int p = 0; p < 2; p++) {
                float2 rr = unpack2(accR[i][p]);
                float2 zz = unpack2(accZ[i][p]);
                float2 ni = unpack2(accNi[i][p]);
                float2 nh = unpack2(accNh[i][p]);
                int d = db + 2 * p;
                float r0 = sigmoidf_(rr.x + sbrz[d]);
                float r1 = sigmoidf_(rr.y + sbrz[d + 1]);
                float z0 = sigmoidf_(zz.x + sbrz[64 + d]);
                float z1 = sigmoidf_(zz.y + sbrz[64 + d + 1]);
                float n0 = tanhf(ni.x + sbni[d]     + r0 * (nh.x + sbnh[d]));
                float n1 = tanhf(ni.y + sbni[d + 1] + r1 * (nh.y + sbnh[d + 1]));
                float h0 = AH[r * AH_STRIDE + 2 * d + 1];
                float h1 = AH[r * AH_STRIDE + 2 * (d + 1) + 1];
                outv[i][2 * p]     = (1.0f - z0) * n0 + z0 * h0;
                outv[i][2 * p + 1] = (1.0f - z1) * n1 + z1 * h1;
            }
        }

        __syncthreads();   // all reads of AH done before 'a'-slot overwrite
#pragma unroll
        for (int i = 0; i < 4; i++) {
            int r = rs + 32 * i;
            int g = row0 + r;
            float4 o4 = make_float4(outv[i][0], outv[i][1], outv[i][2], outv[i][3]);
            if (g < N_NODES)
                *(float4*)&hout[(size_t)g * 64 + db] = o4;
            // stage h_out into 'a' slots for the epilogue (padded rows finite)
            AH[r * AH_STRIDE + 2 * db + 0] = o4.x;
            AH[r * AH_STRIDE + 2 * db + 2] = o4.y;
            AH[r * AH_STRIDE + 2 * db + 4] = o4.z;
            AH[r * AH_STRIDE + 2 * db + 6] = o4.w;
        }
        __syncthreads();

        if (do_wh) {
            // epilogue: wh_next = h_out @ W^T + b
            ull acc[4][2];
            {
                ull b0 = pack2f(sbb[db], sbb[db + 1]);
                ull b1 = pack2f(sbb[db + 2], sbb[db + 3]);
#pragma unroll
                for (int i = 0; i < 4; i++) { acc[i][0] = b0; acc[i][1] = b1; }
            }
#pragma unroll 8
            for (int k = 0; k < 64; k++) {
                const ull* wr = (const ull*)&WTs[k * 64 + db];
                ull w0 = wr[0], w1 = wr[1];
#pragma unroll
                for (int i = 0; i < 4; i++) {
                    float x = AH[(rs + 32 * i) * AH_STRIDE + 2 * k];
                    ull x2 = pack2f(x, x);
                    acc[i][0] = ffma2(x2, w0, acc[i][0]);
                    acc[i][1] = ffma2(x2, w1, acc[i][1]);
                }
            }
#pragma unroll
            for (int i = 0; i < 4; i++) {
                int g = row0 + rs + 32 * i;
                if (g < N_NODES) {
                    float2 a = unpack2(acc[i][0]);
                    float2 c = unpack2(acc[i][1]);
                    *(float4*)&g_wh[(size_t)g * 64 + db] = make_float4(a.x, a.y, c.x, c.y);
                }
            }
        }
        __syncthreads();   // before next tile overwrites AH
    }
}

// ------------------------- launch --------------------------------------------
extern "C" void kernel_launch(void* const* d_in, const int* in_sizes, int n_in,
                              void* d_out, int out_size) {
    const float *node_in = 0, *W = 0, *b = 0, *Wih = 0, *Whh = 0, *bih = 0, *bhh = 0;
    const int *src = 0, *dst = 0;
    int n12288 = 0, n192 = 0, n800k = 0;
    for (int i = 0; i < n_in; i++) {
        switch (in_sizes[i]) {
            case N_NODES * D: node_in = (const float*)d_in[i]; break;
            case D * D:       W = (const float*)d_in[i]; break;
            case D:           b = (const float*)d_in[i]; break;
            case 3 * D * D:
                if (n12288++ == 0) Wih = (const float*)d_in[i];
                else               Whh = (const float*)d_in[i];
                break;
            case 3 * D:
                if (n192++ == 0) bih = (const float*)d_in[i];
                else             bhh = (const float*)d_in[i];
                break;
            case N_EDGES:
                if (n800k++ == 0) src = (const int*)d_in[i];
                else              dst = (const int*)d_in[i];
                break;
            default: break;
        }
    }
    float* h = (float*)d_out;

    const int GEMM1_SMEM = (64 * 64 + 128 * T_STRIDE + 64) * 4;
    // gru: 2*12288 + 4096 + 128*136 + 320 floats = 45,824 * 4 = 183,296 B
    const int GRU_SMEM = (2 * 12288 + 64 * 64 + 128 * AH_STRIDE + 320) * 4;
    cudaFuncSetAttribute(gemm1_kernel, cudaFuncAttributeMaxDynamicSharedMemorySize, GEMM1_SMEM);
    cudaFuncSetAttribute(gru_kernel,   cudaFuncAttributeMaxDynamicSharedMemorySize, GRU_SMEM);

    // one-time prep + parallel CSR build
    prep_kernel<<<(N_NODES + 255) / 256, 256>>>(W, Wih, Whh, bih, bhh);
    count_kernel<<<(N_EDGES + 255) / 256, 256>>>(dst);
    chunksum_kernel<<<N_CHUNKS, 256>>>();
    chunkscan_kernel<<<1, 256>>>();
    rowptr_kernel<<<N_CHUNKS, 256>>>();
    fill_kernel<<<(N_EDGES + 255) / 256, 256>>>(src, dst);

    const int agg_grid = (N_NODES * 32 + 255) / 256;

    gemm1_kernel<<<N_TILES, 512, GEMM1_SMEM>>>(node_in, b);     // wh for step 0

    // step 0
    agg_kernel<<<agg_grid, 256>>>();
    gru_kernel<<<GRU_GRID, 512, GRU_SMEM>>>(node_in, h, b, 1);  // also wh for step 1
    // step 1
    agg_kernel<<<agg_grid, 256>>>();
    gru_kernel<<<GRU_GRID, 512, GRU_SMEM>>>(h, h, b, 1);        // also wh for step 2
    // step 2
    agg_kernel<<<agg_grid, 256>>>();
    gru_kernel<<<GRU_GRID, 512, GRU_SMEM>>>(h, h, b, 0);
}